// round 5
// baseline (speedup 1.0000x reference)
#include <cuda_runtime.h>
#include <cuda_bf16.h>
#include <math.h>
#include <stdint.h>

#define N_LEVELS   16
#define N_DENSE    10
#define HASH_BITS  19
#define TABLE_SIZE (1u << HASH_BITS)
#define HASH_MASK  (TABLE_SIZE - 1u)
#define PRIME2     2654435761u
#define PRIME3     805459861u

// Dense quad grid: entry(cx,cy,cz) = 32B =
//   { zpair(cx,cy,cz), zpair(cx,cy+1%res,cz) },  zpair = {tab[h(z)], tab[h(z+1%res)]}
#define DENSE_CAP  4300000
__device__ float4 g_quad[2 * DENSE_CAP];               // ~137.6 MB

// Quad hash tables for pow2-res hashed levels (12: 256, 15: 512):
//   entry s = { tab[s], tab[s+Dz], tab[s+Dy], tab[s+Dy+Dz] } (mod-2^32 deltas, &MASK)
#define MAX_PAIRED 2
__device__ float4 g_ztabq[2 * MAX_PAIRED * TABLE_SIZE];  // ~33.6 MB

struct Params {
    int res[N_LEVELS];
    int dense_base[N_DENSE];          // entry offset per dense level
    int fill_prefix[N_DENSE + 1];
    unsigned pair_mask;
    int      pair_slot[N_LEVELS];
    int      slot_level[MAX_PAIRED];
    unsigned slot_dz[MAX_PAIRED];
    unsigned slot_dy[MAX_PAIRED];
    int      n_paired;
};

// XLA-GPU lowers f32 divide to div.full.f32 (approx). The hash trunc
// amplifies 1-ulp differences into wrong indices; reproduce the instruction.
__device__ __forceinline__ float div_full(float a, float b) {
    float r;
    asm("div.full.f32 %0, %1, %2;" : "=f"(r) : "f"(a), "f"(b));
    return r;
}

__device__ __forceinline__ unsigned hash_part(int c, float fres, unsigned prime) {
    float cfrac = div_full((float)c, fres);
    float qf = __fmul_rn(__fmul_rn(__fadd_rn(cfrac, 1.0f), 0.5f), 262144.0f);
    unsigned q = (unsigned)qf;           // positive -> trunc == astype(int64)
    return q * prime;                     // uint32 wrap OK: 2^19 | 2^32
}

// ---------------------------------------------------------------------------
// Fill dense quad grid: one thread per corner. Gathers own value; z+1 value
// comes from lane+1 via shfl (cz is fastest-varying) except at row/warp
// boundaries (rare re-gather). Writes the 16B zpair into two quad halves.
// NOTE: no early return before the shfl (full-mask warp collective).
// ---------------------------------------------------------------------------
__global__ void __launch_bounds__(256)
fill_quad_kernel(const float* __restrict__ tables, Params p, int total)
{
    int tid0 = blockIdx.x * blockDim.x + threadIdx.x;
    bool valid = tid0 < total;
    int tid = valid ? tid0 : (total - 1);

    int level = 0;
#pragma unroll
    for (int i = 0; i < N_DENSE; i++)
        if (tid >= p.fill_prefix[i + 1]) level = i + 1;

    int r   = tid - p.fill_prefix[level];
    int res = p.res[level];
    int cz = r % res;
    int t  = r / res;
    int cy = t % res;
    int cx = t / res;

    float fres = (float)res;
    unsigned hx = hash_part(cx, fres, 1u);
    unsigned hy = hash_part(cy, fres, PRIME2);
    unsigned hz = hash_part(cz, fres, PRIME3);

    const float2* tab = reinterpret_cast<const float2*>(tables)
                        + (size_t)level * TABLE_SIZE;
    float2 v = __ldg(tab + ((hx + hy + hz) & HASH_MASK));

    // z+1 neighbor: shfl from lane+1 when it is the same row's next corner
    int lane = threadIdx.x & 31;
    float nx = __shfl_down_sync(0xFFFFFFFFu, v.x, 1);
    float ny = __shfl_down_sync(0xFFFFFFFFu, v.y, 1);
    float2 vn;
    if (cz < res - 1 && lane < 31 && valid) {
        vn = make_float2(nx, ny);
    } else {
        int z1 = (cz + 1 == res) ? 0 : cz + 1;
        unsigned hz1 = hash_part(z1, fres, PRIME3);
        vn = __ldg(tab + ((hx + hy + hz1) & HASH_MASK));
    }

    if (valid) {
        float4 pairv = make_float4(v.x, v.y, vn.x, vn.y);
        size_t base = (size_t)2 * p.dense_base[level];
        int idx  = (cx * res + cy) * res + cz;
        int cym  = (cy == 0) ? res - 1 : cy - 1;
        int idxm = (cx * res + cym) * res + cz;
        g_quad[base + 2 * (size_t)idx]      = pairv;  // half0 (y row) of (cx,cy,cz)
        g_quad[base + 2 * (size_t)idxm + 1] = pairv;  // half1 (y+1 row) of (cx,cy-1,cz)
    }
}

// ---------------------------------------------------------------------------
// Fill quad hash tables for pow2-res levels: fully coalesced streams.
// ---------------------------------------------------------------------------
__global__ void __launch_bounds__(256)
fill_ztabq_kernel(const float* __restrict__ tables, Params p, int total)
{
    int tid = blockIdx.x * blockDim.x + threadIdx.x;
    if (tid >= total) return;
    int slot   = tid >> HASH_BITS;
    unsigned s = tid & HASH_MASK;
    int level  = p.slot_level[slot];
    unsigned Dz = p.slot_dz[slot];
    unsigned Dy = p.slot_dy[slot];

    const float2* tab = reinterpret_cast<const float2*>(tables)
                        + (size_t)level * TABLE_SIZE;
    float2 a = __ldg(tab + s);
    float2 b = __ldg(tab + ((s + Dz) & HASH_MASK));
    float2 c = __ldg(tab + ((s + Dy) & HASH_MASK));
    float2 d = __ldg(tab + ((s + Dy + Dz) & HASH_MASK));
    size_t base = (size_t)2 * (((size_t)slot << HASH_BITS) + s);
    g_ztabq[base]     = make_float4(a.x, a.y, b.x, b.y);   // y0: z0, z1
    g_ztabq[base + 1] = make_float4(c.x, c.y, d.x, d.y);   // y1: z0, z1
}

// ---------------------------------------------------------------------------
// Main kernel: ONE WARP PER POINT. lane = 2*level + yrow.
// Even lane handles the y0 corner row (both x corners), odd lane y1.
// Lane pairs read consecutive 16B halves of 32B quad entries -> coalesced.
// ---------------------------------------------------------------------------
__global__ void __launch_bounds__(256)
hash_encoding_kernel(const float* __restrict__ x,
                     const float* __restrict__ tables,
                     float* __restrict__ out,
                     Params p,
                     int n_points)
{
    int gtid = blockIdx.x * blockDim.x + threadIdx.x;
    int n    = gtid >> 5;
    if (n >= n_points) return;
    int lane  = gtid & 31;
    int level = lane >> 1;
    int yrow  = lane & 1;

    // cooperative x load + broadcast
    float xr = 0.f;
    if (lane < 3) xr = x[(size_t)n * 3 + lane];
    float xv[3];
    xv[0] = __shfl_sync(0xFFFFFFFFu, xr, 0);
    xv[1] = __shfl_sync(0xFFFFFFFFu, xr, 1);
    xv[2] = __shfl_sync(0xFFFFFFFFu, xr, 2);
#pragma unroll
    for (int d = 0; d < 3; d++) xv[d] = fminf(fmaxf(xv[d], -1.0f), 1.0f);

    const int   res  = p.res[level];
    const float fres = (float)res;

    int   c0[3], c1[3];
    float w[3][2];
#pragma unroll
    for (int d = 0; d < 3; d++) {
        float coord = xv[d] * fres;
        float cf    = floorf(coord);
        float lc    = coord - cf;
        int   ci    = (int)cf;
        w[d][0] = 1.0f - lc;
        w[d][1] = lc;
        int a = ci % res; if (a < 0) a += res;
        c0[d] = a;
        int b = a + 1;    if (b == res) b = 0;
        c1[d] = b;
    }

    float wx0 = w[0][0], wx1 = w[0][1];
    float wy  = w[1][yrow];
    float wz0 = w[2][0], wz1 = w[2][1];

    float part0, part1;   // this lane's y-row partial (2 features)

    if (level < N_DENSE) {
        // ---- dense quad path: 2 lane-pair-coalesced LDG.128 ----
        const float4* q = g_quad + (size_t)2 * p.dense_base[level];
        int rr = res;
        size_t i0 = (size_t)(c0[0] * rr + c0[1]) * rr + c0[2];
        size_t i1 = (size_t)(c1[0] * rr + c0[1]) * rr + c0[2];
        float4 a = __ldg(q + 2 * i0 + yrow);   // x0: (y_row,z0),(y_row,z1)
        float4 b = __ldg(q + 2 * i1 + yrow);   // x1
        part0 = wy * (wx0 * (wz0 * a.x + wz1 * a.z) +
                      wx1 * (wz0 * b.x + wz1 * b.z));
        part1 = wy * (wx0 * (wz0 * a.y + wz1 * a.w) +
                      wx1 * (wz0 * b.y + wz1 * b.w));
    } else {
        unsigned hp0[2], hp1[2], hp2[2];
        hp0[0] = hash_part(c0[0], fres, 1u);
        hp0[1] = hash_part(c1[0], fres, 1u);
        hp1[0] = hash_part(c0[1], fres, PRIME2);
        hp1[1] = hash_part(c1[1], fres, PRIME2);
        hp2[0] = hash_part(c0[2], fres, PRIME3);
        hp2[1] = hash_part(c1[2], fres, PRIME3);
        const float2* tab = reinterpret_cast<const float2*>(tables)
                            + (size_t)level * TABLE_SIZE;

        bool paired = (p.pair_mask >> level) & 1u;
        if (paired && c0[1] != res - 1 && c0[2] != res - 1) {
            // ---- quad hash path: 2 lane-pair-coalesced LDG.128 ----
            const float4* zt = g_ztabq
                + (size_t)2 * ((size_t)p.pair_slot[level] << HASH_BITS);
            unsigned syz = hp1[0] + hp2[0];
            unsigned s0 = (hp0[0] + syz) & HASH_MASK;
            unsigned s1 = (hp0[1] + syz) & HASH_MASK;
            float4 a = __ldg(zt + 2 * (size_t)s0 + yrow);
            float4 b = __ldg(zt + 2 * (size_t)s1 + yrow);
            part0 = wy * (wx0 * (wz0 * a.x + wz1 * a.z) +
                          wx1 * (wz0 * b.x + wz1 * b.z));
            part1 = wy * (wx0 * (wz0 * a.y + wz1 * a.w) +
                          wx1 * (wz0 * b.y + wz1 * b.w));
        } else {
            // ---- general hashed path: 4 gathers for this y-row ----
            unsigned hy = hp1[yrow];
            float2 f00 = __ldg(tab + ((hp0[0] + hy + hp2[0]) & HASH_MASK));
            float2 f01 = __ldg(tab + ((hp0[0] + hy + hp2[1]) & HASH_MASK));
            float2 f10 = __ldg(tab + ((hp0[1] + hy + hp2[0]) & HASH_MASK));
            float2 f11 = __ldg(tab + ((hp0[1] + hy + hp2[1]) & HASH_MASK));
            part0 = wy * (wx0 * (wz0 * f00.x + wz1 * f01.x) +
                          wx1 * (wz0 * f10.x + wz1 * f11.x));
            part1 = wy * (wx0 * (wz0 * f00.y + wz1 * f01.y) +
                          wx1 * (wz0 * f10.y + wz1 * f11.y));
        }
    }

    // combine y0 + y1 rows across the lane pair
    float tot0 = part0 + __shfl_xor_sync(0xFFFFFFFFu, part0, 1);
    float tot1 = part1 + __shfl_xor_sync(0xFFFFFFFFu, part1, 1);

    if (yrow == 0) {
        reinterpret_cast<float2*>(out)[(size_t)n * N_LEVELS + level] =
            make_float2(tot0, tot1);
    }
}

extern "C" void kernel_launch(void* const* d_in, const int* in_sizes, int n_in,
                              void* d_out, int out_size)
{
    const float* x      = (const float*)d_in[0];
    const float* tables = (const float*)d_in[1];
    float*       out    = (float*)d_out;

    int n_points = in_sizes[0] / 3;

    Params p;
    for (int i = 0; i < N_LEVELS; i++) {
        double r = 16.0 * pow(32.0, (double)i / 15.0);   // host libm pow
        p.res[i] = (int)r;
    }
    int off = 0;
    p.fill_prefix[0] = 0;
    for (int i = 0; i < N_DENSE; i++) {
        p.dense_base[i] = off;
        int cnt = p.res[i] * p.res[i] * p.res[i];
        off += cnt;
        p.fill_prefix[i + 1] = p.fill_prefix[i] + cnt;
    }

    p.pair_mask = 0;
    p.n_paired  = 0;
    for (int i = 0; i < N_LEVELS; i++) p.pair_slot[i] = 0;
    for (int lvl = N_DENSE; lvl < N_LEVELS && p.n_paired < MAX_PAIRED; lvl++) {
        int r = p.res[lvl];
        if ((r & (r - 1)) == 0 && r <= 131072) {
            unsigned step = 131072u / (unsigned)r;
            p.pair_mask |= (1u << lvl);
            p.pair_slot[lvl] = p.n_paired;
            p.slot_level[p.n_paired] = lvl;
            p.slot_dz[p.n_paired] = PRIME3 * step;
            p.slot_dy[p.n_paired] = PRIME2 * step;
            p.n_paired++;
        }
    }

    int threads = 256;

    int total_fill = p.fill_prefix[N_DENSE];
    fill_quad_kernel<<<(total_fill + threads - 1) / threads, threads>>>(
        tables, p, total_fill);

    if (p.n_paired > 0) {
        int total_z = p.n_paired * (int)TABLE_SIZE;
        fill_ztabq_kernel<<<(total_z + threads - 1) / threads, threads>>>(
            tables, p, total_z);
    }

    long long total = (long long)n_points * 32;
    int blocks = (int)((total + threads - 1) / threads);
    hash_encoding_kernel<<<blocks, threads>>>(x, tables, out, p, n_points);
}